// round 1
// baseline (speedup 1.0000x reference)
#include <cuda_runtime.h>
#include <math.h>

#define SLEN  2048
#define BSZ   4
#define DM    1024
#define NH    16
#define DH    64
#define SLOTD 32
#define KD    16
#define NKEYS 256
#define NTOT  48
#define NTOK  (SLEN*BSZ)      /* 8192 */
#define NBH   (BSZ*NH)        /* 64   */
#define CHUNK 64
#define NCH   (SLEN/CHUNK)    /* 32   */

// ---------------- scratch (device globals; no allocation allowed) ----------
__device__ float g_qraw[NTOK*NTOT*KD];
__device__ float g_q   [NTOK*NTOT*KD];
__device__ float g_keyn[32*NKEYS*KD];
__device__ float g_hq  [NBH*SLEN*DH];
__device__ float g_hk  [NBH*SLEN*DH];
__device__ float g_hv  [NBH*SLEN*DH];
__device__ float g_S   [NBH*NCH*DH*DH];
__device__ float g_ksum[NBH*NCH*DH];
__device__ float g_lo  [NTOK*DM];
__device__ float g_attn[NTOK*DM];

// ---------------- key normalization ---------------------------------------
__global__ void k_norm_keys(const float* __restrict__ keys){
  int r = blockIdx.x*blockDim.x + threadIdx.x;
  if(r >= 32*NKEYS) return;
  const float* src = keys + (size_t)r*KD;
  float s = 0.f;
  #pragma unroll
  for(int i=0;i<KD;i++) s += src[i]*src[i];
  float inv = 1.f/sqrtf(s);
  #pragma unroll
  for(int i=0;i<KD;i++) g_keyn[(size_t)r*KD+i] = src[i]*inv;
}

// ---------------- generic NT SGEMM: C[M,N] = A[M,K] * B[N,K]^T --------------
__global__ void __launch_bounds__(256)
k_sgemm_nt(const float* __restrict__ A, const float* __restrict__ B,
           float* __restrict__ C, int M, int N, int K){
  __shared__ float As[8][128];
  __shared__ float Bs[8][128];
  int tid  = threadIdx.x;
  int lrow = tid>>1, lk = (tid&1)*4;
  const float* Ap = A + (size_t)(blockIdx.y*128 + lrow)*K + lk;
  const float* Bp = B + (size_t)(blockIdx.x*128 + lrow)*K + lk;
  int tx = tid&15, ty = tid>>4;
  float acc[8][8];
  #pragma unroll
  for(int i=0;i<8;i++)
    #pragma unroll
    for(int j=0;j<8;j++) acc[i][j]=0.f;

  for(int k0=0;k0<K;k0+=8){
    float4 av = *(const float4*)(Ap + k0);
    float4 bv = *(const float4*)(Bp + k0);
    __syncthreads();
    As[lk+0][lrow]=av.x; As[lk+1][lrow]=av.y; As[lk+2][lrow]=av.z; As[lk+3][lrow]=av.w;
    Bs[lk+0][lrow]=bv.x; Bs[lk+1][lrow]=bv.y; Bs[lk+2][lrow]=bv.z; Bs[lk+3][lrow]=bv.w;
    __syncthreads();
    #pragma unroll
    for(int kk=0;kk<8;kk++){
      float4 a0 = *(const float4*)&As[kk][ty*8];
      float4 a1 = *(const float4*)&As[kk][ty*8+4];
      float4 b0 = *(const float4*)&Bs[kk][tx*8];
      float4 b1 = *(const float4*)&Bs[kk][tx*8+4];
      float a[8]={a0.x,a0.y,a0.z,a0.w,a1.x,a1.y,a1.z,a1.w};
      float b[8]={b0.x,b0.y,b0.z,b0.w,b1.x,b1.y,b1.z,b1.w};
      #pragma unroll
      for(int i=0;i<8;i++)
        #pragma unroll
        for(int j=0;j<8;j++) acc[i][j]=fmaf(a[i],b[j],acc[i][j]);
    }
  }
  #pragma unroll
  for(int i=0;i<8;i++){
    float* cp = C + (size_t)(blockIdx.y*128 + ty*8 + i)*N + blockIdx.x*128 + tx*8;
    *(float4*)cp     = make_float4(acc[i][0],acc[i][1],acc[i][2],acc[i][3]);
    *(float4*)(cp+4) = make_float4(acc[i][4],acc[i][5],acc[i][6],acc[i][7]);
  }
}

// ---------------- q bias + LN over groups of 16 ----------------------------
__global__ void k_q_ln(const float* __restrict__ bq, const float* __restrict__ gq,
                       const float* __restrict__ bln){
  int g = blockIdx.x*blockDim.x + threadIdx.x;
  if(g >= NTOK*NTOT) return;
  int n = g % NTOT;
  const float* src = g_qraw + (size_t)g*KD;
  const float* bb  = bq + n*KD;
  float v[KD]; float m=0.f;
  #pragma unroll
  for(int i=0;i<KD;i++){ v[i]=src[i]+bb[i]; m+=v[i]; }
  m *= (1.f/KD);
  float var=0.f;
  #pragma unroll
  for(int i=0;i<KD;i++){ float d=v[i]-m; var+=d*d; }
  var *= (1.f/KD);
  float inv = rsqrtf(var + 1e-5f);
  #pragma unroll
  for(int i=0;i<KD;i++) g_q[(size_t)g*KD+i] = (v[i]-m)*inv*gq[i] + bln[i];
}

// ---------------- PKM: scores, top-8, softmax-mix, res, mem proj, elu ------
// grid (48 slots, 32 token-chunks), 256 threads; each warp: 32 tokens in groups of 4.
__global__ void __launch_bounds__(256)
k_pkm(const float* __restrict__ values, const float* __restrict__ Wres,
      const float* __restrict__ bres, const float* __restrict__ Wmem,
      const float* __restrict__ bmem){
  extern __shared__ float sm[];
  float* key_s = sm;                 // [16][256]
  float* val_s = key_s + 16*256;     // [256][32]
  float* wm_s  = val_s + 256*32;     // [64][33]
  float* wr_s  = wm_s  + 64*33;      // [32][17]
  float* br_s  = wr_s  + 32*17;      // [32]
  float* bm_s  = br_s  + 32;         // [64]

  int n = blockIdx.x, neff = n & 31;
  int tid = threadIdx.x, lane = tid & 31, warp = tid >> 5;

  for(int idx=tid; idx<256*16; idx+=256){
    int j=idx>>4, d=idx&15;
    key_s[d*256+j] = g_keyn[((size_t)neff*256 + j)*16 + d];
  }
  for(int idx=tid; idx<256*32; idx+=256) val_s[idx] = values[(size_t)neff*256*32 + idx];
  for(int idx=tid; idx<64*32;  idx+=256) wm_s[(idx>>5)*33 + (idx&31)] = Wmem[idx];
  for(int idx=tid; idx<32*16;  idx+=256) wr_s[(idx>>4)*17 + (idx&15)] = Wres[idx];
  if(tid<32) br_s[tid]=bres[tid];
  if(tid<64) bm_s[tid]=bmem[tid];
  __syncthreads();

  float* dst; bool act;
  if(n<16){ dst=g_hk; act=true; } else if(n<32){ dst=g_hv; act=false; } else { dst=g_hq; act=true; }
  int hh = n & 15;

  int tokbase0 = blockIdx.y*256 + warp*32;
  int sub = lane>>4, d0 = lane&15;

  for(int grp=0; grp<8; grp++){
    int tb = tokbase0 + grp*4;
    float qv0 = g_q[(size_t)(tb+sub  )*(NTOT*KD) + n*KD + d0];
    float qv1 = g_q[(size_t)(tb+2+sub)*(NTOT*KD) + n*KD + d0];

    float sc[4][8];
    #pragma unroll
    for(int t=0;t<4;t++)
      #pragma unroll
      for(int i=0;i<8;i++) sc[t][i]=0.f;

    #pragma unroll
    for(int d=0;d<16;d++){
      float kk[8];
      #pragma unroll
      for(int i=0;i<8;i++) kk[i]=key_s[d*256 + lane + (i<<5)];
      float qa = __shfl_sync(0xffffffffu, qv0, d);
      float qb = __shfl_sync(0xffffffffu, qv0, d+16);
      float qc = __shfl_sync(0xffffffffu, qv1, d);
      float qd = __shfl_sync(0xffffffffu, qv1, d+16);
      #pragma unroll
      for(int i=0;i<8;i++){
        sc[0][i]=fmaf(qa,kk[i],sc[0][i]);
        sc[1][i]=fmaf(qb,kk[i],sc[1][i]);
        sc[2][i]=fmaf(qc,kk[i],sc[2][i]);
        sc[3][i]=fmaf(qd,kk[i],sc[3][i]);
      }
    }

    #pragma unroll
    for(int tt=0;tt<4;tt++){
      int tok = tb+tt;
      float s[8];
      #pragma unroll
      for(int i=0;i<8;i++) s[i]=sc[tt][i];

      float wv[8]; int ji[8];
      #pragma unroll
      for(int r=0;r<8;r++){
        float m=s[0]; int mi=0;
        #pragma unroll
        for(int i=1;i<8;i++) if(s[i]>m){ m=s[i]; mi=i; }
        int gi = lane + (mi<<5);
        #pragma unroll
        for(int off=16;off;off>>=1){
          float om=__shfl_xor_sync(0xffffffffu,m,off);
          int   oi=__shfl_xor_sync(0xffffffffu,gi,off);
          if(om>m || (om==m && oi<gi)){ m=om; gi=oi; }
        }
        wv[r]=m; ji[r]=gi;
        if((gi&31)==lane){
          int sl=gi>>5;
          #pragma unroll
          for(int i=0;i<8;i++) if(sl==i) s[i]=-1e30f;
        }
      }

      float mx = wv[0];
      float w[8]; float wsum=0.f;
      #pragma unroll
      for(int r=0;r<8;r++){ w[r]=expf(wv[r]-mx); wsum+=w[r]; }
      float invw = 1.f/wsum;

      float o = 0.f;
      #pragma unroll
      for(int r=0;r<8;r++) o += w[r]*val_s[ji[r]*32 + lane];
      o *= invw;

      // residual path: q @ Wres^T + bres
      float racc = br_s[lane];
      #pragma unroll
      for(int d=0;d<16;d++){
        float qd = (tt<2) ? __shfl_sync(0xffffffffu,qv0,(tt&1)*16+d)
                          : __shfl_sync(0xffffffffu,qv1,(tt&1)*16+d);
        racc = fmaf(qd, wr_s[lane*17+d], racc);
      }
      o += racc;

      // mem projection: out64 = o32 @ Wmem^T + bmem
      float u0 = bm_s[lane], u1 = bm_s[lane+32];
      #pragma unroll
      for(int e=0;e<32;e++){
        float oe = __shfl_sync(0xffffffffu, o, e);
        u0 = fmaf(oe, wm_s[lane*33+e],      u0);
        u1 = fmaf(oe, wm_s[(lane+32)*33+e], u1);
      }
      if(act){
        u0 = (u0>0.f)? u0+1.f : expf(u0);   // elu(x)+1
        u1 = (u1>0.f)? u1+1.f : expf(u1);
      }
      int b = tok & 3, t = tok >> 2;
      size_t ob = ((size_t)((b*NH+hh)*SLEN + t))*DH;
      dst[ob + lane]      = u0;
      dst[ob + 32 + lane] = u1;
    }
  }
}

// ---------------- pass A: per-chunk S = K^T V and ksum ---------------------
__global__ void __launch_bounds__(256) k_passA(){
  __shared__ float Ks[64][68];
  __shared__ float Vs[64][68];
  int bh=blockIdx.x, c=blockIdx.y;
  int tid=threadIdx.x;
  size_t base=((size_t)bh*SLEN + c*CHUNK)*DH;
  for(int idx=tid; idx<64*64; idx+=256){
    int t=idx>>6, e=idx&63;
    Ks[t][e]=g_hk[base+idx];
    Vs[t][e]=g_hv[base+idx];
  }
  __syncthreads();
  int tx=tid&15, ty=tid>>4;
  float acc[4][4];
  #pragma unroll
  for(int i=0;i<4;i++)
    #pragma unroll
    for(int j=0;j<4;j++) acc[i][j]=0.f;
  for(int t=0;t<64;t++){
    float4 a=*(const float4*)&Ks[t][ty*4];
    float4 b=*(const float4*)&Vs[t][tx*4];
    float av[4]={a.x,a.y,a.z,a.w}, bv[4]={b.x,b.y,b.z,b.w};
    #pragma unroll
    for(int i=0;i<4;i++)
      #pragma unroll
      for(int j=0;j<4;j++) acc[i][j]=fmaf(av[i],bv[j],acc[i][j]);
  }
  size_t sb=((size_t)bh*NCH + c)*DH*DH;
  #pragma unroll
  for(int i=0;i<4;i++)
    *(float4*)&g_S[sb + (size_t)(ty*4+i)*64 + tx*4] =
        make_float4(acc[i][0],acc[i][1],acc[i][2],acc[i][3]);
  if(tid<64){
    float s=0.f;
    for(int t=0;t<64;t++) s+=Ks[t][tid];
    g_ksum[((size_t)bh*NCH+c)*DH + tid]=s;
  }
}

// ---------------- pass B: exclusive prefix over chunks ---------------------
__global__ void __launch_bounds__(256) k_passB(){
  int bh=blockIdx.x, tid=threadIdx.x;
  float run[16];
  #pragma unroll
  for(int i=0;i<16;i++) run[i]=0.f;
  for(int c=0;c<NCH;c++){
    size_t base=((size_t)bh*NCH+c)*DH*DH;
    #pragma unroll
    for(int i=0;i<16;i++){
      size_t idx=base + tid + 256*i;
      float t=g_S[idx]; g_S[idx]=run[i]; run[i]+=t;
    }
  }
  if(tid<64){
    float r=0.f;
    for(int c=0;c<NCH;c++){
      size_t j=((size_t)bh*NCH+c)*DH + tid;
      float t=g_ksum[j]; g_ksum[j]=r; r+=t;
    }
  }
}

// ---------------- pass C: chunk output + denom -----------------------------
__global__ void __launch_bounds__(256) k_passC(){
  extern __shared__ float smc[];
  float* Qt = smc;            // [64][68]  transposed: Qt[d][t]
  float* Kt = Qt + 64*68;     // [64][68]  Kt[d][s]
  float* Vs = Kt + 64*68;     // [64][68]  Vs[s][e]
  float* Ws = Vs + 64*68;     // [64][68]  Ws[d][e]
  float* Am = Ws + 64*68;     // [64][68]  masked A[t][s]
  float* kp = Am + 64*68;     // [64]
  float* dn = kp + 64;        // [64]
  int bh=blockIdx.x, c=blockIdx.y;
  int tid=threadIdx.x;
  size_t base=((size_t)bh*SLEN + c*CHUNK)*DH;
  size_t sb=((size_t)bh*NCH+c)*DH*DH;
  for(int idx=tid; idx<64*64; idx+=256){
    int t=idx>>6, d=idx&63;
    Qt[d*68+t]=g_hq[base+idx];
    Kt[d*68+t]=g_hk[base+idx];
    Vs[t*68+d]=g_hv[base+idx];
    Ws[t*68+d]=g_S[sb+idx];
  }
  if(tid<64) kp[tid]=g_ksum[((size_t)bh*NCH+c)*DH + tid];
  __syncthreads();

  int tx=tid&15, ty=tid>>4;
  float acc[4][4];
  #pragma unroll
  for(int i=0;i<4;i++)
    #pragma unroll
    for(int j=0;j<4;j++) acc[i][j]=0.f;
  for(int d=0;d<64;d++){
    float4 a=*(const float4*)&Qt[d*68+ty*4];
    float4 b=*(const float4*)&Kt[d*68+tx*4];
    float av[4]={a.x,a.y,a.z,a.w}, bv[4]={b.x,b.y,b.z,b.w};
    #pragma unroll
    for(int i=0;i<4;i++)
      #pragma unroll
      for(int j=0;j<4;j++) acc[i][j]=fmaf(av[i],bv[j],acc[i][j]);
  }
  #pragma unroll
  for(int i=0;i<4;i++)
    #pragma unroll
    for(int j=0;j<4;j++){
      int t=ty*4+i, s=tx*4+j;
      Am[t*68+s] = (s<=t)? acc[i][j] : 0.f;
    }
  __syncthreads();

  if(tid<64){
    int t=tid; float s=0.f;
    for(int j=0;j<64;j++) s+=Am[t*68+j];
    for(int d=0;d<64;d++) s=fmaf(Qt[d*68+t],kp[d],s);
    dn[t]=s;
  }
  __syncthreads();

  float o[4][4];
  #pragma unroll
  for(int i=0;i<4;i++)
    #pragma unroll
    for(int j=0;j<4;j++) o[i][j]=0.f;
  for(int s=0;s<64;s++){
    float4 b=*(const float4*)&Vs[s*68+tx*4];
    float bv[4]={b.x,b.y,b.z,b.w};
    float av[4];
    #pragma unroll
    for(int i=0;i<4;i++) av[i]=Am[(ty*4+i)*68+s];
    #pragma unroll
    for(int i=0;i<4;i++)
      #pragma unroll
      for(int j=0;j<4;j++) o[i][j]=fmaf(av[i],bv[j],o[i][j]);
  }
  for(int d=0;d<64;d++){
    float4 a=*(const float4*)&Qt[d*68+ty*4];
    float4 b=*(const float4*)&Ws[d*68+tx*4];
    float av[4]={a.x,a.y,a.z,a.w}, bv[4]={b.x,b.y,b.z,b.w};
    #pragma unroll
    for(int i=0;i<4;i++)
      #pragma unroll
      for(int j=0;j<4;j++) o[i][j]=fmaf(av[i],bv[j],o[i][j]);
  }

  int bb=bh>>4, hh=bh&15;
  const float scale = 0.125f; // 1/sqrt(64)
  #pragma unroll
  for(int i=0;i<4;i++){
    int t=ty*4+i;
    float r = scale/(dn[t]+1e-5f);
    int tg = c*CHUNK + t;
    size_t off = ((size_t)(tg*BSZ + bb))*DM + hh*DH + tx*4;
    *(float4*)&g_lo[off] = make_float4(o[i][0]*r,o[i][1]*r,o[i][2]*r,o[i][3]*r);
  }
}

// ---------------- final residual LN over 1024 ------------------------------
__global__ void __launch_bounds__(256)
k_out_ln(const float* __restrict__ h, const float* __restrict__ g,
         const float* __restrict__ bb, float* __restrict__ out){
  int row=blockIdx.x, tid=threadIdx.x;
  const float* hp = h      + (size_t)row*DM;
  const float* ap = g_attn + (size_t)row*DM;
  float v[4]; float s=0.f;
  #pragma unroll
  for(int i=0;i<4;i++){ int c=tid+256*i; v[i]=hp[c]+ap[c]; s+=v[i]; }
  __shared__ float red[8];
  __shared__ float bc[2];
  #pragma unroll
  for(int off=16;off;off>>=1) s+=__shfl_xor_sync(0xffffffffu,s,off);
  if((tid&31)==0) red[tid>>5]=s;
  __syncthreads();
  if(tid==0){
    float t=0.f;
    #pragma unroll
    for(int i=0;i<8;i++) t+=red[i];
    bc[0]=t*(1.f/DM);
  }
  __syncthreads();
  float m=bc[0];
  float vv=0.f;
  #pragma unroll
  for(int i=0;i<4;i++){ float d=v[i]-m; vv+=d*d; }
  #pragma unroll
  for(int off=16;off;off>>=1) vv+=__shfl_xor_sync(0xffffffffu,vv,off);
  if((tid&31)==0) red[tid>>5]=vv;
  __syncthreads();
  if(tid==0){
    float t=0.f;
    #pragma unroll
    for(int i=0;i<8;i++) t+=red[i];
    bc[1]=rsqrtf(t*(1.f/DM)+1e-5f);
  }
  __syncthreads();
  float inv=bc[1];
  #pragma unroll
  for(int i=0;i<4;i++){
    int c=tid+256*i;
    out[(size_t)row*DM+c]=(v[i]-m)*inv*g[c]+bb[c];
  }
}

// ---------------- host launcher --------------------------------------------
extern "C" void kernel_launch(void* const* d_in, const int* in_sizes, int n_in,
                              void* d_out, int out_size){
  const float* h    = (const float*)d_in[0];
  const float* Wq   = (const float*)d_in[1];
  const float* bq   = (const float*)d_in[2];
  const float* gq   = (const float*)d_in[3];
  const float* bln  = (const float*)d_in[4];
  const float* keys = (const float*)d_in[5];
  const float* vals = (const float*)d_in[6];
  const float* Wres = (const float*)d_in[7];
  const float* bres = (const float*)d_in[8];
  const float* Wmem = (const float*)d_in[9];
  const float* bmem = (const float*)d_in[10];
  const float* Wo   = (const float*)d_in[11];
  const float* gout = (const float*)d_in[12];
  const float* bout = (const float*)d_in[13];
  float* out = (float*)d_out;

  float *qraw, *lo, *attn;
  cudaGetSymbolAddress((void**)&qraw, g_qraw);
  cudaGetSymbolAddress((void**)&lo,   g_lo);
  cudaGetSymbolAddress((void**)&attn, g_attn);

  const int SMEM_PKM = (16*256 + 256*32 + 64*33 + 32*17 + 32 + 64)*4; // 60160
  const int SMEM_C   = (5*64*68 + 64 + 64)*4;                          // 87552
  cudaFuncSetAttribute(k_pkm,   cudaFuncAttributeMaxDynamicSharedMemorySize, SMEM_PKM);
  cudaFuncSetAttribute(k_passC, cudaFuncAttributeMaxDynamicSharedMemorySize, SMEM_C);

  k_norm_keys<<<(32*NKEYS+127)/128, 128>>>(keys);
  k_sgemm_nt<<<dim3(6,64), 256>>>(h, Wq, qraw, NTOK, NTOT*KD, DM);
  k_q_ln<<<(NTOK*NTOT+255)/256, 256>>>(bq, gq, bln);
  k_pkm<<<dim3(48,32), 256, SMEM_PKM>>>(vals, Wres, bres, Wmem, bmem);
  k_passA<<<dim3(NBH,NCH), 256>>>();
  k_passB<<<NBH, 256>>>();
  k_passC<<<dim3(NBH,NCH), 256, SMEM_C>>>();
  k_sgemm_nt<<<dim3(8,64), 256>>>(lo, Wo, attn, NTOK, DM, DM);
  k_out_ln<<<NTOK, 256>>>(h, gout, bout, out);
}

// round 2
// speedup vs baseline: 1.0095x; 1.0095x over previous
#include <cuda_runtime.h>
#include <math.h>

#define SLEN  2048
#define BSZ   4
#define DM    1024
#define NH    16
#define DH    64
#define SLOTD 32
#define KD    16
#define NKEYS 256
#define NTOT  48
#define NTOK  (SLEN*BSZ)      /* 8192 */
#define NBH   (BSZ*NH)        /* 64   */
#define CHUNK 64
#define NCH   (SLEN/CHUNK)    /* 32   */

// ---------------- scratch (device globals; no allocation allowed) ----------
__device__ float g_qraw[NTOK*NTOT*KD];
__device__ float g_q   [NTOK*NTOT*KD];
__device__ float g_keyn[32*NKEYS*KD];
__device__ float g_hq  [NBH*SLEN*DH];
__device__ float g_hk  [NBH*SLEN*DH];
__device__ float g_hv  [NBH*SLEN*DH];
__device__ float g_S   [NBH*NCH*DH*DH];
__device__ float g_ksum[NBH*NCH*DH];
__device__ float g_lo  [NTOK*DM];
__device__ float g_attn[NTOK*DM];

// ---------------- key normalization ---------------------------------------
__global__ void k_norm_keys(const float* __restrict__ keys){
  int r = blockIdx.x*blockDim.x + threadIdx.x;
  if(r >= 32*NKEYS) return;
  const float* src = keys + (size_t)r*KD;
  float s = 0.f;
  #pragma unroll
  for(int i=0;i<KD;i++) s += src[i]*src[i];
  float inv = 1.f/sqrtf(s);
  #pragma unroll
  for(int i=0;i<KD;i++) g_keyn[(size_t)r*KD+i] = src[i]*inv;
}

// ---------------- generic NT SGEMM: C[M,N] = A[M,K] * B[N,K]^T --------------
__global__ void __launch_bounds__(256)
k_sgemm_nt(const float* __restrict__ A, const float* __restrict__ B,
           float* __restrict__ C, int M, int N, int K){
  __shared__ float As[8][128];
  __shared__ float Bs[8][128];
  int tid  = threadIdx.x;
  int lrow = tid>>1, lk = (tid&1)*4;
  const float* Ap = A + (size_t)(blockIdx.y*128 + lrow)*K + lk;
  const float* Bp = B + (size_t)(blockIdx.x*128 + lrow)*K + lk;
  int tx = tid&15, ty = tid>>4;
  float acc[8][8];
  #pragma unroll
  for(int i=0;i<8;i++)
    #pragma unroll
    for(int j=0;j<8;j++) acc[i][j]=0.f;

  for(int k0=0;k0<K;k0+=8){
    float4 av = *(const float4*)(Ap + k0);
    float4 bv = *(const float4*)(Bp + k0);
    __syncthreads();
    As[lk+0][lrow]=av.x; As[lk+1][lrow]=av.y; As[lk+2][lrow]=av.z; As[lk+3][lrow]=av.w;
    Bs[lk+0][lrow]=bv.x; Bs[lk+1][lrow]=bv.y; Bs[lk+2][lrow]=bv.z; Bs[lk+3][lrow]=bv.w;
    __syncthreads();
    #pragma unroll
    for(int kk=0;kk<8;kk++){
      float4 a0 = *(const float4*)&As[kk][ty*8];
      float4 a1 = *(const float4*)&As[kk][ty*8+4];
      float4 b0 = *(const float4*)&Bs[kk][tx*8];
      float4 b1 = *(const float4*)&Bs[kk][tx*8+4];
      float a[8]={a0.x,a0.y,a0.z,a0.w,a1.x,a1.y,a1.z,a1.w};
      float b[8]={b0.x,b0.y,b0.z,b0.w,b1.x,b1.y,b1.z,b1.w};
      #pragma unroll
      for(int i=0;i<8;i++)
        #pragma unroll
        for(int j=0;j<8;j++) acc[i][j]=fmaf(a[i],b[j],acc[i][j]);
    }
  }
  #pragma unroll
  for(int i=0;i<8;i++){
    float* cp = C + (size_t)(blockIdx.y*128 + ty*8 + i)*N + blockIdx.x*128 + tx*8;
    *(float4*)cp     = make_float4(acc[i][0],acc[i][1],acc[i][2],acc[i][3]);
    *(float4*)(cp+4) = make_float4(acc[i][4],acc[i][5],acc[i][6],acc[i][7]);
  }
}

// ---------------- q bias + LN over groups of 16 ----------------------------
__global__ void k_q_ln(const float* __restrict__ bq, const float* __restrict__ gq,
                       const float* __restrict__ bln){
  int g = blockIdx.x*blockDim.x + threadIdx.x;
  if(g >= NTOK*NTOT) return;
  int n = g % NTOT;
  const float* src = g_qraw + (size_t)g*KD;
  const float* bb  = bq + n*KD;
  float v[KD]; float m=0.f;
  #pragma unroll
  for(int i=0;i<KD;i++){ v[i]=src[i]+bb[i]; m+=v[i]; }
  m *= (1.f/KD);
  float var=0.f;
  #pragma unroll
  for(int i=0;i<KD;i++){ float d=v[i]-m; var+=d*d; }
  var *= (1.f/KD);
  float inv = rsqrtf(var + 1e-5f);
  #pragma unroll
  for(int i=0;i<KD;i++) g_q[(size_t)g*KD+i] = (v[i]-m)*inv*gq[i] + bln[i];
}

// ---------------- PKM: scores, top-8, softmax-mix, res, mem proj, elu ------
// grid (48 slots, 32 token-chunks), 256 threads; each warp: 32 tokens in groups of 4.
__global__ void __launch_bounds__(256)
k_pkm(const float* __restrict__ values, const float* __restrict__ Wres,
      const float* __restrict__ bres, const float* __restrict__ Wmem,
      const float* __restrict__ bmem){
  extern __shared__ float sm[];
  float* key_s = sm;                 // [16][256]
  float* val_s = key_s + 16*256;     // [256][32]
  float* wm_s  = val_s + 256*32;     // [64][33]
  float* wr_s  = wm_s  + 64*33;      // [32][17]
  float* br_s  = wr_s  + 32*17;      // [32]
  float* bm_s  = br_s  + 32;         // [64]

  int n = blockIdx.x, neff = n & 31;
  int tid = threadIdx.x, lane = tid & 31, warp = tid >> 5;

  for(int idx=tid; idx<256*16; idx+=256){
    int j=idx>>4, d=idx&15;
    key_s[d*256+j] = g_keyn[((size_t)neff*256 + j)*16 + d];
  }
  for(int idx=tid; idx<256*32; idx+=256) val_s[idx] = values[(size_t)neff*256*32 + idx];
  for(int idx=tid; idx<64*32;  idx+=256) wm_s[(idx>>5)*33 + (idx&31)] = Wmem[idx];
  for(int idx=tid; idx<32*16;  idx+=256) wr_s[(idx>>4)*17 + (idx&15)] = Wres[idx];
  if(tid<32) br_s[tid]=bres[tid];
  if(tid<64) bm_s[tid]=bmem[tid];
  __syncthreads();

  float* dst; bool act;
  if(n<16){ dst=g_hk; act=true; } else if(n<32){ dst=g_hv; act=false; } else { dst=g_hq; act=true; }
  int hh = n & 15;

  int tokbase0 = blockIdx.y*256 + warp*32;
  int sub = lane>>4, d0 = lane&15;

  for(int grp=0; grp<8; grp++){
    int tb = tokbase0 + grp*4;
    float qv0 = g_q[(size_t)(tb+sub  )*(NTOT*KD) + n*KD + d0];
    float qv1 = g_q[(size_t)(tb+2+sub)*(NTOT*KD) + n*KD + d0];

    float sc[4][8];
    #pragma unroll
    for(int t=0;t<4;t++)
      #pragma unroll
      for(int i=0;i<8;i++) sc[t][i]=0.f;

    #pragma unroll
    for(int d=0;d<16;d++){
      float kk[8];
      #pragma unroll
      for(int i=0;i<8;i++) kk[i]=key_s[d*256 + lane + (i<<5)];
      float qa = __shfl_sync(0xffffffffu, qv0, d);
      float qb = __shfl_sync(0xffffffffu, qv0, d+16);
      float qc = __shfl_sync(0xffffffffu, qv1, d);
      float qd = __shfl_sync(0xffffffffu, qv1, d+16);
      #pragma unroll
      for(int i=0;i<8;i++){
        sc[0][i]=fmaf(qa,kk[i],sc[0][i]);
        sc[1][i]=fmaf(qb,kk[i],sc[1][i]);
        sc[2][i]=fmaf(qc,kk[i],sc[2][i]);
        sc[3][i]=fmaf(qd,kk[i],sc[3][i]);
      }
    }

    #pragma unroll
    for(int tt=0;tt<4;tt++){
      int tok = tb+tt;
      float s[8];
      #pragma unroll
      for(int i=0;i<8;i++) s[i]=sc[tt][i];

      float wv[8]; int ji[8];
      #pragma unroll
      for(int r=0;r<8;r++){
        float m=s[0]; int mi=0;
        #pragma unroll
        for(int i=1;i<8;i++) if(s[i]>m){ m=s[i]; mi=i; }
        int gi = lane + (mi<<5);
        #pragma unroll
        for(int off=16;off;off>>=1){
          float om=__shfl_xor_sync(0xffffffffu,m,off);
          int   oi=__shfl_xor_sync(0xffffffffu,gi,off);
          if(om>m || (om==m && oi<gi)){ m=om; gi=oi; }
        }
        wv[r]=m; ji[r]=gi;
        if((gi&31)==lane){
          int sl=gi>>5;
          #pragma unroll
          for(int i=0;i<8;i++) if(sl==i) s[i]=-1e30f;
        }
      }

      float mx = wv[0];
      float w[8]; float wsum=0.f;
      #pragma unroll
      for(int r=0;r<8;r++){ w[r]=expf(wv[r]-mx); wsum+=w[r]; }
      float invw = 1.f/wsum;

      float o = 0.f;
      #pragma unroll
      for(int r=0;r<8;r++) o += w[r]*val_s[ji[r]*32 + lane];
      o *= invw;

      // residual path: q @ Wres^T + bres
      float racc = br_s[lane];
      #pragma unroll
      for(int d=0;d<16;d++){
        float qd = (tt<2) ? __shfl_sync(0xffffffffu,qv0,(tt&1)*16+d)
                          : __shfl_sync(0xffffffffu,qv1,(tt&1)*16+d);
        racc = fmaf(qd, wr_s[lane*17+d], racc);
      }
      o += racc;

      // mem projection: out64 = o32 @ Wmem^T + bmem
      float u0 = bm_s[lane], u1 = bm_s[lane+32];
      #pragma unroll
      for(int e=0;e<32;e++){
        float oe = __shfl_sync(0xffffffffu, o, e);
        u0 = fmaf(oe, wm_s[lane*33+e],      u0);
        u1 = fmaf(oe, wm_s[(lane+32)*33+e], u1);
      }
      if(act){
        u0 = (u0>0.f)? u0+1.f : expf(u0);   // elu(x)+1
        u1 = (u1>0.f)? u1+1.f : expf(u1);
      }
      int b = tok & 3, t = tok >> 2;
      size_t ob = ((size_t)((b*NH+hh)*SLEN + t))*DH;
      dst[ob + lane]      = u0;
      dst[ob + 32 + lane] = u1;
    }
  }
}

// ---------------- pass A: per-chunk S = K^T V and ksum ---------------------
__global__ void __launch_bounds__(256) k_passA(){
  __shared__ float Ks[64][68];
  __shared__ float Vs[64][68];
  int bh=blockIdx.x, c=blockIdx.y;
  int tid=threadIdx.x;
  size_t base=((size_t)bh*SLEN + c*CHUNK)*DH;
  for(int idx=tid; idx<64*64; idx+=256){
    int t=idx>>6, e=idx&63;
    Ks[t][e]=g_hk[base+idx];
    Vs[t][e]=g_hv[base+idx];
  }
  __syncthreads();
  int tx=tid&15, ty=tid>>4;
  float acc[4][4];
  #pragma unroll
  for(int i=0;i<4;i++)
    #pragma unroll
    for(int j=0;j<4;j++) acc[i][j]=0.f;
  for(int t=0;t<64;t++){
    float4 a=*(const float4*)&Ks[t][ty*4];
    float4 b=*(const float4*)&Vs[t][tx*4];
    float av[4]={a.x,a.y,a.z,a.w}, bv[4]={b.x,b.y,b.z,b.w};
    #pragma unroll
    for(int i=0;i<4;i++)
      #pragma unroll
      for(int j=0;j<4;j++) acc[i][j]=fmaf(av[i],bv[j],acc[i][j]);
  }
  size_t sb=((size_t)bh*NCH + c)*DH*DH;
  #pragma unroll
  for(int i=0;i<4;i++)
    *(float4*)&g_S[sb + (size_t)(ty*4+i)*64 + tx*4] =
        make_float4(acc[i][0],acc[i][1],acc[i][2],acc[i][3]);
  if(tid<64){
    float s=0.f;
    for(int t=0;t<64;t++) s+=Ks[t][tid];
    g_ksum[((size_t)bh*NCH+c)*DH + tid]=s;
  }
}

// ---------------- pass B: exclusive prefix over chunks ---------------------
__global__ void __launch_bounds__(256) k_passB(){
  int bh=blockIdx.x, tid=threadIdx.x;
  float run[16];
  #pragma unroll
  for(int i=0;i<16;i++) run[i]=0.f;
  for(int c=0;c<NCH;c++){
    size_t base=((size_t)bh*NCH+c)*DH*DH;
    #pragma unroll
    for(int i=0;i<16;i++){
      size_t idx=base + tid + 256*i;
      float t=g_S[idx]; g_S[idx]=run[i]; run[i]+=t;
    }
  }
  if(tid<64){
    float r=0.f;
    for(int c=0;c<NCH;c++){
      size_t j=((size_t)bh*NCH+c)*DH + tid;
      float t=g_ksum[j]; g_ksum[j]=r; r+=t;
    }
  }
}

// ---------------- pass C: chunk output + denom -----------------------------
__global__ void __launch_bounds__(256) k_passC(){
  extern __shared__ float smc[];
  float* Qt = smc;            // [64][68]  transposed: Qt[d][t]
  float* Kt = Qt + 64*68;     // [64][68]  Kt[d][s]
  float* Vs = Kt + 64*68;     // [64][68]  Vs[s][e]
  float* Ws = Vs + 64*68;     // [64][68]  Ws[d][e]
  float* Am = Ws + 64*68;     // [64][68]  masked A[t][s]
  float* kp = Am + 64*68;     // [64]
  float* dn = kp + 64;        // [64]
  int bh=blockIdx.x, c=blockIdx.y;
  int tid=threadIdx.x;
  size_t base=((size_t)bh*SLEN + c*CHUNK)*DH;
  size_t sb=((size_t)bh*NCH+c)*DH*DH;
  for(int idx=tid; idx<64*64; idx+=256){
    int t=idx>>6, d=idx&63;
    Qt[d*68+t]=g_hq[base+idx];
    Kt[d*68+t]=g_hk[base+idx];
    Vs[t*68+d]=g_hv[base+idx];
    Ws[t*68+d]=g_S[sb+idx];
  }
  if(tid<64) kp[tid]=g_ksum[((size_t)bh*NCH+c)*DH + tid];
  __syncthreads();

  int tx=tid&15, ty=tid>>4;
  float acc[4][4];
  #pragma unroll
  for(int i=0;i<4;i++)
    #pragma unroll
    for(int j=0;j<4;j++) acc[i][j]=0.f;
  for(int d=0;d<64;d++){
    float4 a=*(const float4*)&Qt[d*68+ty*4];
    float4 b=*(const float4*)&Kt[d*68+tx*4];
    float av[4]={a.x,a.y,a.z,a.w}, bv[4]={b.x,b.y,b.z,b.w};
    #pragma unroll
    for(int i=0;i<4;i++)
      #pragma unroll
      for(int j=0;j<4;j++) acc[i][j]=fmaf(av[i],bv[j],acc[i][j]);
  }
  #pragma unroll
  for(int i=0;i<4;i++)
    #pragma unroll
    for(int j=0;j<4;j++){
      int t=ty*4+i, s=tx*4+j;
      Am[t*68+s] = (s<=t)? acc[i][j] : 0.f;
    }
  __syncthreads();

  if(tid<64){
    int t=tid; float s=0.f;
    for(int j=0;j<64;j++) s+=Am[t*68+j];
    for(int d=0;d<64;d++) s=fmaf(Qt[d*68+t],kp[d],s);
    dn[t]=s;
  }
  __syncthreads();

  float o[4][4];
  #pragma unroll
  for(int i=0;i<4;i++)
    #pragma unroll
    for(int j=0;j<4;j++) o[i][j]=0.f;
  for(int s=0;s<64;s++){
    float4 b=*(const float4*)&Vs[s*68+tx*4];
    float bv[4]={b.x,b.y,b.z,b.w};
    float av[4];
    #pragma unroll
    for(int i=0;i<4;i++) av[i]=Am[(ty*4+i)*68+s];
    #pragma unroll
    for(int i=0;i<4;i++)
      #pragma unroll
      for(int j=0;j<4;j++) o[i][j]=fmaf(av[i],bv[j],o[i][j]);
  }
  for(int d=0;d<64;d++){
    float4 a=*(const float4*)&Qt[d*68+ty*4];
    float4 b=*(const float4*)&Ws[d*68+tx*4];
    float av[4]={a.x,a.y,a.z,a.w}, bv[4]={b.x,b.y,b.z,b.w};
    #pragma unroll
    for(int i=0;i<4;i++)
      #pragma unroll
      for(int j=0;j<4;j++) o[i][j]=fmaf(av[i],bv[j],o[i][j]);
  }

  int bb=bh>>4, hh=bh&15;
  const float scale = 0.125f; // 1/sqrt(64)
  #pragma unroll
  for(int i=0;i<4;i++){
    int t=ty*4+i;
    float r = scale/(dn[t]+1e-5f);
    int tg = c*CHUNK + t;
    size_t off = ((size_t)(tg*BSZ + bb))*DM + hh*DH + tx*4;
    *(float4*)&g_lo[off] = make_float4(o[i][0]*r,o[i][1]*r,o[i][2]*r,o[i][3]*r);
  }
}

// ---------------- final residual LN over 1024 ------------------------------
__global__ void __launch_bounds__(256)
k_out_ln(const float* __restrict__ h, const float* __restrict__ g,
         const float* __restrict__ bb, float* __restrict__ out){
  int row=blockIdx.x, tid=threadIdx.x;
  const float* hp = h      + (size_t)row*DM;
  const float* ap = g_attn + (size_t)row*DM;
  float v[4]; float s=0.f;
  #pragma unroll
  for(int i=0;i<4;i++){ int c=tid+256*i; v[i]=hp[c]+ap[c]; s+=v[i]; }
  __shared__ float red[8];
  __shared__ float bc[2];
  #pragma unroll
  for(int off=16;off;off>>=1) s+=__shfl_xor_sync(0xffffffffu,s,off);
  if((tid&31)==0) red[tid>>5]=s;
  __syncthreads();
  if(tid==0){
    float t=0.f;
    #pragma unroll
    for(int i=0;i<8;i++) t+=red[i];
    bc[0]=t*(1.f/DM);
  }
  __syncthreads();
  float m=bc[0];
  float vv=0.f;
  #pragma unroll
  for(int i=0;i<4;i++){ float d=v[i]-m; vv+=d*d; }
  #pragma unroll
  for(int off=16;off;off>>=1) vv+=__shfl_xor_sync(0xffffffffu,vv,off);
  if((tid&31)==0) red[tid>>5]=vv;
  __syncthreads();
  if(tid==0){
    float t=0.f;
    #pragma unroll
    for(int i=0;i<8;i++) t+=red[i];
    bc[1]=rsqrtf(t*(1.f/DM)+1e-5f);
  }
  __syncthreads();
  float inv=bc[1];
  #pragma unroll
  for(int i=0;i<4;i++){
    int c=tid+256*i;
    out[(size_t)row*DM+c]=(v[i]-m)*inv*g[c]+bb[c];
  }
}

// ---------------- host launcher --------------------------------------------
extern "C" void kernel_launch(void* const* d_in, const int* in_sizes, int n_in,
                              void* d_out, int out_size){
  const float* h    = (const float*)d_in[0];
  const float* Wq   = (const float*)d_in[1];
  const float* bq   = (const float*)d_in[2];
  const float* gq   = (const float*)d_in[3];
  const float* bln  = (const float*)d_in[4];
  const float* keys = (const float*)d_in[5];
  const float* vals = (const float*)d_in[6];
  const float* Wres = (const float*)d_in[7];
  const float* bres = (const float*)d_in[8];
  const float* Wmem = (const float*)d_in[9];
  const float* bmem = (const float*)d_in[10];
  const float* Wo   = (const float*)d_in[11];
  const float* gout = (const float*)d_in[12];
  const float* bout = (const float*)d_in[13];
  float* out = (float*)d_out;

  float *qraw, *lo, *attn;
  cudaGetSymbolAddress((void**)&qraw, g_qraw);
  cudaGetSymbolAddress((void**)&lo,   g_lo);
  cudaGetSymbolAddress((void**)&attn, g_attn);

  const int SMEM_PKM = (16*256 + 256*32 + 64*33 + 32*17 + 32 + 64)*4; // 60160
  const int SMEM_C   = (5*64*68 + 64 + 64)*4;                          // 87552
  cudaFuncSetAttribute(k_pkm,   cudaFuncAttributeMaxDynamicSharedMemorySize, SMEM_PKM);
  cudaFuncSetAttribute(k_passC, cudaFuncAttributeMaxDynamicSharedMemorySize, SMEM_C);

  k_norm_keys<<<(32*NKEYS+127)/128, 128>>>(keys);
  k_sgemm_nt<<<dim3(6,64), 256>>>(h, Wq, qraw, NTOK, NTOT*KD, DM);
  k_q_ln<<<(NTOK*NTOT+255)/256, 256>>>(bq, gq, bln);
  k_pkm<<<dim3(48,32), 256, SMEM_PKM>>>(vals, Wres, bres, Wmem, bmem);
  k_passA<<<dim3(NBH,NCH), 256>>>();
  k_passB<<<NBH, 256>>>();
  k_passC<<<dim3(NBH,NCH), 256, SMEM_C>>>();
  k_sgemm_nt<<<dim3(8,64), 256>>>(lo, Wo, attn, NTOK, DM, DM);
  k_out_ln<<<NTOK, 256>>>(h, gout, bout, out);
}